// round 1
// baseline (speedup 1.0000x reference)
#include <cuda_runtime.h>
#include <cstddef>

#define HID 128
#define NMAX 50000

// Scratch (device globals are the sanctioned alloc-free scratch mechanism)
__device__ float g_H1[(size_t)NMAX * HID];      // relu(nf @ W1 + b1)
__device__ float g_pooled[(size_t)NMAX * HID];  // segment-sum target

// ---------------------------------------------------------------------------
// GEMM: Y = relu(X @ W + b) [+ res]. X:[nrows,128], W:[128,128] row-major.
// Block: 256 threads, 64-row M-tile, full 128-col N.
// Thread (rg=tid/32, cg=tid%32) computes rows rg*8..+7, cols cg*4..+3.
// Within a warp rg is constant -> xs reads are broadcasts; ws reads are
// conflict-free LDS.128 (lane*16B within a 512B row).
// ---------------------------------------------------------------------------
template <bool RESIDUAL>
__global__ __launch_bounds__(256) void gemm_relu_kernel(
    const float* __restrict__ X, const float* __restrict__ W,
    const float* __restrict__ b, const float* __restrict__ res,
    float* __restrict__ Y, int nrows)
{
    extern __shared__ float smem[];
    float* ws = smem;                                   // 128*128 floats (64KB)
    float (*xs)[HID] = (float(*)[HID])(smem + HID * HID); // 64*128 floats (32KB)

    const int tid = threadIdx.x;
    const int row0 = blockIdx.x * 64;

    // Load W (coalesced) into shared
    #pragma unroll
    for (int i = tid; i < HID * HID; i += 256) ws[i] = W[i];

    // Load X tile (coalesced along k)
    #pragma unroll
    for (int i = tid; i < 64 * HID; i += 256) {
        int r = i >> 7, k = i & 127;
        int gr = row0 + r;
        xs[r][k] = (gr < nrows) ? X[(size_t)gr * HID + k] : 0.f;
    }
    __syncthreads();

    const int cg = tid & 31;
    const int rg = tid >> 5;
    const int c0 = cg << 2;

    float acc[8][4];
    #pragma unroll
    for (int i = 0; i < 8; i++)
        #pragma unroll
        for (int j = 0; j < 4; j++) acc[i][j] = 0.f;

    #pragma unroll 4
    for (int k = 0; k < HID; k++) {
        float4 w = *(const float4*)&ws[k * HID + c0];
        #pragma unroll
        for (int i = 0; i < 8; i++) {
            float x = xs[rg * 8 + i][k];
            acc[i][0] = fmaf(x, w.x, acc[i][0]);
            acc[i][1] = fmaf(x, w.y, acc[i][1]);
            acc[i][2] = fmaf(x, w.z, acc[i][2]);
            acc[i][3] = fmaf(x, w.w, acc[i][3]);
        }
    }

    float4 bias = *(const float4*)&b[c0];
    #pragma unroll
    for (int i = 0; i < 8; i++) {
        int row = row0 + rg * 8 + i;
        if (row < nrows) {
            float4 o;
            o.x = fmaxf(acc[i][0] + bias.x, 0.f);
            o.y = fmaxf(acc[i][1] + bias.y, 0.f);
            o.z = fmaxf(acc[i][2] + bias.z, 0.f);
            o.w = fmaxf(acc[i][3] + bias.w, 0.f);
            if (RESIDUAL) {
                float4 rr = *(const float4*)&res[(size_t)row * HID + c0];
                o.x += rr.x; o.y += rr.y; o.z += rr.z; o.w += rr.w;
            }
            *(float4*)&Y[(size_t)row * HID + c0] = o;
        }
    }
}

// ---------------------------------------------------------------------------
// Zero the pooled scratch (vectorized)
// ---------------------------------------------------------------------------
__global__ void zero_pooled_kernel(int n4)
{
    int i = blockIdx.x * blockDim.x + threadIdx.x;
    if (i < n4) ((float4*)g_pooled)[i] = make_float4(0.f, 0.f, 0.f, 0.f);
}

// ---------------------------------------------------------------------------
// Scatter: one warp per edge. Lane l handles floats [l*4, l*4+4).
// pooled[tgt[e]] += norm[e] * H1[src[e]] via vector reduction (red.v4.f32).
// ---------------------------------------------------------------------------
__global__ __launch_bounds__(256) void scatter_kernel(
    const int* __restrict__ src, const int* __restrict__ tgt,
    const float* __restrict__ norm, int nedges)
{
    int e = blockIdx.x * 8 + (threadIdx.x >> 5);
    if (e >= nedges) return;
    int lane = threadIdx.x & 31;

    int   s = __ldg(&src[e]);
    int   t = __ldg(&tgt[e]);
    float n = __ldg(&norm[e]);

    float4 v = *(const float4*)&g_H1[(size_t)s * HID + lane * 4];
    v.x *= n; v.y *= n; v.z *= n; v.w *= n;

    float* dst = &g_pooled[(size_t)t * HID + lane * 4];
    asm volatile("red.global.add.v4.f32 [%0], {%1, %2, %3, %4};"
                 :: "l"(dst), "f"(v.x), "f"(v.y), "f"(v.z), "f"(v.w)
                 : "memory");
}

// ---------------------------------------------------------------------------
// Launch
// ---------------------------------------------------------------------------
extern "C" void kernel_launch(void* const* d_in, const int* in_sizes, int n_in,
                              void* d_out, int out_size)
{
    const float* nf   = (const float*)d_in[0];
    const int*   src  = (const int*)d_in[1];
    const int*   tgt  = (const int*)d_in[2];
    const float* norm = (const float*)d_in[3];
    const float* W1   = (const float*)d_in[4];
    const float* b1   = (const float*)d_in[5];
    const float* W2   = (const float*)d_in[6];
    const float* b2   = (const float*)d_in[7];
    float*       out  = (float*)d_out;

    const int nnodes = in_sizes[0] / HID;
    const int nedges = in_sizes[1];

    const size_t smem = (size_t)(HID * HID + 64 * HID) * sizeof(float); // 96KB
    cudaFuncSetAttribute(gemm_relu_kernel<false>,
                         cudaFuncAttributeMaxDynamicSharedMemorySize, (int)smem);
    cudaFuncSetAttribute(gemm_relu_kernel<true>,
                         cudaFuncAttributeMaxDynamicSharedMemorySize, (int)smem);

    float *H1 = nullptr, *pooled = nullptr;
    cudaGetSymbolAddress((void**)&H1, g_H1);
    cudaGetSymbolAddress((void**)&pooled, g_pooled);

    const int n4 = nnodes * (HID / 4);
    zero_pooled_kernel<<<(n4 + 255) / 256, 256>>>(n4);

    const int gblocks = (nnodes + 63) / 64;
    gemm_relu_kernel<false><<<gblocks, 256, smem>>>(nf, W1, b1, nullptr, H1, nnodes);

    scatter_kernel<<<(nedges + 7) / 8, 256>>>(src, tgt, norm, nedges);

    gemm_relu_kernel<true><<<gblocks, 256, smem>>>(pooled, W2, b2, nf, out, nnodes);
}

// round 2
// speedup vs baseline: 1.0638x; 1.0638x over previous
#include <cuda_runtime.h>
#include <cstddef>

#define HID 128
#define NMAX 50000

// Scratch (device globals = sanctioned alloc-free scratch)
__device__ float g_H1[(size_t)NMAX * HID];      // relu(nf @ W1 + b1)
__device__ float g_pooled[(size_t)NMAX * HID];  // segment-sum target

// ---------------------------------------------------------------------------
// GEMM: Y = relu(X @ W + b) [+ res]. X:[nrows,128], W:[128,128] row-major.
// 256 threads, 64-row M-tile, full 128-col N.
// Thread (rg=tid/32, cg=tid%32) computes rows rg*8..+7, cols cg*4..+3.
// Math uses packed fp32 FFMA2 (fma.rn.f32x2): the 4 output cols form 2
// b64 accumulator pairs; W pairs come free from the LDS.128 (ulonglong2
// view), x is duplicated via mov.b64 {x,x} on the alu pipe (overlaps the
// fma pipe). ZERO=true additionally zeroes g_pooled rows [row0,row0+64).
// ---------------------------------------------------------------------------
template <bool RESIDUAL, bool ZERO>
__global__ __launch_bounds__(256) void gemm_relu_kernel(
    const float* __restrict__ X, const float* __restrict__ W,
    const float* __restrict__ b, const float* __restrict__ res,
    float* __restrict__ Y, int nrows)
{
    extern __shared__ float smem[];
    float* ws = smem;                                     // 128*128 f32 (64KB)
    float (*xs)[HID] = (float(*)[HID])(smem + HID * HID); // 64*128 f32 (32KB)

    const int tid = threadIdx.x;
    const int row0 = blockIdx.x * 64;

    // Load W (coalesced)
    #pragma unroll
    for (int i = tid; i < HID * HID; i += 256) ws[i] = W[i];

    // Load X tile (coalesced along k)
    #pragma unroll
    for (int i = tid; i < 64 * HID; i += 256) {
        int r = i >> 7, k = i & 127;
        int gr = row0 + r;
        xs[r][k] = (gr < nrows) ? X[(size_t)gr * HID + k] : 0.f;
    }

    if (ZERO) {
        // Zero this block's 64-row slice of g_pooled (ordered before the
        // scatter kernel by the kernel-launch boundary).
        float4 z = make_float4(0.f, 0.f, 0.f, 0.f);
        #pragma unroll
        for (int i = tid; i < 64 * (HID / 4); i += 256) {
            int r = i >> 5, q = i & 31;
            int gr = row0 + r;
            if (gr < nrows)
                *(float4*)&g_pooled[(size_t)gr * HID + q * 4] = z;
        }
    }
    __syncthreads();

    const int cg = tid & 31;
    const int rg = tid >> 5;
    const int c0 = cg << 2;

    // acc[i][0] packs cols (c0, c0+1); acc[i][1] packs (c0+2, c0+3)
    unsigned long long acc[8][2];
    #pragma unroll
    for (int i = 0; i < 8; i++) { acc[i][0] = 0ull; acc[i][1] = 0ull; }

    #pragma unroll 2
    for (int k = 0; k < HID; k += 4) {
        ulonglong2 wp[4];
        #pragma unroll
        for (int kk = 0; kk < 4; kk++)
            wp[kk] = *(const ulonglong2*)&ws[(k + kk) * HID + c0];

        #pragma unroll
        for (int i = 0; i < 8; i++) {
            float4 xv = *(const float4*)&xs[rg * 8 + i][k];
            float xa[4] = {xv.x, xv.y, xv.z, xv.w};
            #pragma unroll
            for (int kk = 0; kk < 4; kk++) {
                unsigned long long xx;
                asm("mov.b64 %0, {%1, %1};" : "=l"(xx) : "f"(xa[kk]));
                asm("fma.rn.f32x2 %0, %1, %2, %0;"
                    : "+l"(acc[i][0]) : "l"(xx), "l"(wp[kk].x));
                asm("fma.rn.f32x2 %0, %1, %2, %0;"
                    : "+l"(acc[i][1]) : "l"(xx), "l"(wp[kk].y));
            }
        }
    }

    float4 bias = *(const float4*)&b[c0];
    #pragma unroll
    for (int i = 0; i < 8; i++) {
        int row = row0 + rg * 8 + i;
        if (row < nrows) {
            float a0, a1, a2, a3;
            asm("mov.b64 {%0, %1}, %2;" : "=f"(a0), "=f"(a1) : "l"(acc[i][0]));
            asm("mov.b64 {%0, %1}, %2;" : "=f"(a2), "=f"(a3) : "l"(acc[i][1]));
            float4 o;
            o.x = fmaxf(a0 + bias.x, 0.f);
            o.y = fmaxf(a1 + bias.y, 0.f);
            o.z = fmaxf(a2 + bias.z, 0.f);
            o.w = fmaxf(a3 + bias.w, 0.f);
            if (RESIDUAL) {
                float4 rr = *(const float4*)&res[(size_t)row * HID + c0];
                o.x += rr.x; o.y += rr.y; o.z += rr.z; o.w += rr.w;
            }
            *(float4*)&Y[(size_t)row * HID + c0] = o;
        }
    }
}

// ---------------------------------------------------------------------------
// Scatter: one warp per edge. Lane l handles floats [l*4, l*4+4).
// pooled[tgt[e]] += norm[e] * H1[src[e]] via red.global.add.v4.f32.
// ---------------------------------------------------------------------------
__global__ __launch_bounds__(256) void scatter_kernel(
    const int* __restrict__ src, const int* __restrict__ tgt,
    const float* __restrict__ norm, int nedges)
{
    int e = blockIdx.x * 8 + (threadIdx.x >> 5);
    if (e >= nedges) return;
    int lane = threadIdx.x & 31;

    int   s = __ldg(&src[e]);
    int   t = __ldg(&tgt[e]);
    float n = __ldg(&norm[e]);

    float4 v = *(const float4*)&g_H1[(size_t)s * HID + lane * 4];
    v.x *= n; v.y *= n; v.z *= n; v.w *= n;

    float* dst = &g_pooled[(size_t)t * HID + lane * 4];
    asm volatile("red.global.add.v4.f32 [%0], {%1, %2, %3, %4};"
                 :: "l"(dst), "f"(v.x), "f"(v.y), "f"(v.z), "f"(v.w)
                 : "memory");
}

// ---------------------------------------------------------------------------
// Launch
// ---------------------------------------------------------------------------
extern "C" void kernel_launch(void* const* d_in, const int* in_sizes, int n_in,
                              void* d_out, int out_size)
{
    const float* nf   = (const float*)d_in[0];
    const int*   src  = (const int*)d_in[1];
    const int*   tgt  = (const int*)d_in[2];
    const float* norm = (const float*)d_in[3];
    const float* W1   = (const float*)d_in[4];
    const float* b1   = (const float*)d_in[5];
    const float* W2   = (const float*)d_in[6];
    const float* b2   = (const float*)d_in[7];
    float*       out  = (float*)d_out;

    const int nnodes = in_sizes[0] / HID;
    const int nedges = in_sizes[1];

    const size_t smem = (size_t)(HID * HID + 64 * HID) * sizeof(float); // 96KB
    cudaFuncSetAttribute(gemm_relu_kernel<false, true>,
                         cudaFuncAttributeMaxDynamicSharedMemorySize, (int)smem);
    cudaFuncSetAttribute(gemm_relu_kernel<true, false>,
                         cudaFuncAttributeMaxDynamicSharedMemorySize, (int)smem);

    float *H1 = nullptr, *pooled = nullptr;
    cudaGetSymbolAddress((void**)&H1, g_H1);
    cudaGetSymbolAddress((void**)&pooled, g_pooled);

    const int gblocks = (nnodes + 63) / 64;

    // GEMM1: H1 = relu(nf @ W1 + b1); also zeroes g_pooled.
    gemm_relu_kernel<false, true><<<gblocks, 256, smem>>>(
        nf, W1, b1, nullptr, H1, nnodes);

    // Scatter: pooled[tgt] += norm * H1[src]
    scatter_kernel<<<(nedges + 7) / 8, 256>>>(src, tgt, norm, nedges);

    // GEMM2: out = relu(pooled @ W2 + b2) + nf
    gemm_relu_kernel<true, false><<<gblocks, 256, smem>>>(
        pooled, W2, b2, nf, out, nnodes);
}

// round 3
// speedup vs baseline: 1.3562x; 1.2749x over previous
#include <cuda_runtime.h>
#include <cstddef>

#define HID   128
#define NMAX  50000
#define EMAX  800000
#define XPAD  68        // padded row stride of transposed X tile (floats)

// ---- device-global scratch (sanctioned alloc-free mechanism) ----
__device__ float g_H1[(size_t)NMAX * HID];       // relu(nf @ W1 + b1)
__device__ float g_pooled[(size_t)NMAX * HID];   // segment-sum result
__device__ int   g_cnt[NMAX];                    // per-node edge count
__device__ int   g_off[NMAX];                    // CSR offsets
__device__ int   g_cur[NMAX];                    // fill cursors
__device__ int   g_bsum[256];                    // chunk sums / prefixes
__device__ int   g_psrc[EMAX];                   // src reordered by tgt
__device__ float g_pnorm[EMAX];                  // norm reordered by tgt

// ---------------------------------------------------------------------------
// GEMM: Y = relu(X @ W + b) [+ res].  X:[nrows,128], W:[128,128] row-major.
// 256 threads, 64-row M-tile, full 128-col N.
// Packed fp32 FFMA2 with ROW pairing: acc[p][c] = (row r0+2p, row r0+2p+1)
// for col c0+c. The x row-pair comes free from an LDS of the TRANSPOSED
// X tile (xst[k][row], broadcast across the warp); only w needs the
// mov.b64 {w,w} duplication (4 per k, reused across 4 row-pairs).
// ---------------------------------------------------------------------------
template <bool RESIDUAL>
__global__ __launch_bounds__(256) void gemm_relu_kernel(
    const float* __restrict__ X, const float* __restrict__ W,
    const float* __restrict__ b, const float* __restrict__ res,
    float* __restrict__ Y, int nrows)
{
    extern __shared__ float smem[];
    float* ws  = smem;                // [128][128]  64KB
    float* xst = smem + HID * HID;    // [128][XPAD] 34.8KB (transposed tile)

    const int tid  = threadIdx.x;
    const int row0 = blockIdx.x * 64;

    // Load W (coalesced)
    #pragma unroll
    for (int i = tid; i < HID * HID; i += 256) ws[i] = W[i];

    // Load X tile transposed: xst[k][r] = X[row0+r][k]
    // (global read coalesced along k; smem write 4-way conflict via pad=68)
    #pragma unroll
    for (int i = tid; i < 64 * HID; i += 256) {
        int r = i >> 7, k = i & 127;
        int gr = row0 + r;
        xst[k * XPAD + r] = (gr < nrows) ? X[(size_t)gr * HID + k] : 0.f;
    }
    __syncthreads();

    const int cg = tid & 31;
    const int rg = tid >> 5;
    const int c0 = cg << 2;
    const int r0 = rg << 3;

    // acc[p][c]: packed (row r0+2p, row r0+2p+1) at col c0+c
    unsigned long long acc[4][4];
    #pragma unroll
    for (int p = 0; p < 4; p++)
        #pragma unroll
        for (int c = 0; c < 4; c++) acc[p][c] = 0ull;

    #pragma unroll 4
    for (int k = 0; k < HID; k++) {
        // 4 row-pairs, broadcast LDS.128 (address warp-uniform)
        ulonglong2 xa = *(const ulonglong2*)&xst[k * XPAD + r0];
        ulonglong2 xb = *(const ulonglong2*)&xst[k * XPAD + r0 + 4];
        unsigned long long xp[4] = {xa.x, xa.y, xb.x, xb.y};

        float4 wv = *(const float4*)&ws[k * HID + c0];
        unsigned long long wd[4];
        asm("mov.b64 %0, {%1, %1};" : "=l"(wd[0]) : "f"(wv.x));
        asm("mov.b64 %0, {%1, %1};" : "=l"(wd[1]) : "f"(wv.y));
        asm("mov.b64 %0, {%1, %1};" : "=l"(wd[2]) : "f"(wv.z));
        asm("mov.b64 %0, {%1, %1};" : "=l"(wd[3]) : "f"(wv.w));

        #pragma unroll
        for (int p = 0; p < 4; p++)
            #pragma unroll
            for (int c = 0; c < 4; c++)
                asm("fma.rn.f32x2 %0, %1, %2, %0;"
                    : "+l"(acc[p][c]) : "l"(xp[p]), "l"(wd[c]));
    }

    float4 bias = *(const float4*)&b[c0];
    #pragma unroll
    for (int p = 0; p < 4; p++) {
        float lo[4], hi[4];
        #pragma unroll
        for (int c = 0; c < 4; c++)
            asm("mov.b64 {%0, %1}, %2;" : "=f"(lo[c]), "=f"(hi[c]) : "l"(acc[p][c]));

        int rowA = row0 + r0 + 2 * p;
        int rowB = rowA + 1;
        if (rowA < nrows) {
            float4 o;
            o.x = fmaxf(lo[0] + bias.x, 0.f);
            o.y = fmaxf(lo[1] + bias.y, 0.f);
            o.z = fmaxf(lo[2] + bias.z, 0.f);
            o.w = fmaxf(lo[3] + bias.w, 0.f);
            if (RESIDUAL) {
                float4 rr = *(const float4*)&res[(size_t)rowA * HID + c0];
                o.x += rr.x; o.y += rr.y; o.z += rr.z; o.w += rr.w;
            }
            *(float4*)&Y[(size_t)rowA * HID + c0] = o;
        }
        if (rowB < nrows) {
            float4 o;
            o.x = fmaxf(hi[0] + bias.x, 0.f);
            o.y = fmaxf(hi[1] + bias.y, 0.f);
            o.z = fmaxf(hi[2] + bias.z, 0.f);
            o.w = fmaxf(hi[3] + bias.w, 0.f);
            if (RESIDUAL) {
                float4 rr = *(const float4*)&res[(size_t)rowB * HID + c0];
                o.x += rr.x; o.y += rr.y; o.z += rr.z; o.w += rr.w;
            }
            *(float4*)&Y[(size_t)rowB * HID + c0] = o;
        }
    }
}

// ---------------------------------------------------------------------------
// CSR build
// ---------------------------------------------------------------------------
__global__ void zero_cnt_kernel(int nnodes)
{
    int i = blockIdx.x * blockDim.x + threadIdx.x;
    if (i < nnodes) g_cnt[i] = 0;
}

__global__ void hist_kernel(const int* __restrict__ tgt, int nedges)
{
    int e = blockIdx.x * blockDim.x + threadIdx.x;
    if (e < nedges) atomicAdd(&g_cnt[tgt[e]], 1);
}

__global__ __launch_bounds__(256) void bsum_kernel(int nnodes)
{
    __shared__ int sh[256];
    int n = blockIdx.x * 256 + threadIdx.x;
    sh[threadIdx.x] = (n < nnodes) ? g_cnt[n] : 0;
    __syncthreads();
    #pragma unroll
    for (int d = 128; d > 0; d >>= 1) {
        if (threadIdx.x < d) sh[threadIdx.x] += sh[threadIdx.x + d];
        __syncthreads();
    }
    if (threadIdx.x == 0) g_bsum[blockIdx.x] = sh[0];
}

__global__ __launch_bounds__(256) void scan_bsum_kernel(int nchunk)
{
    __shared__ int sh[256];
    int t = threadIdx.x;
    int v = (t < nchunk) ? g_bsum[t] : 0;
    sh[t] = v;
    __syncthreads();
    #pragma unroll
    for (int d = 1; d < 256; d <<= 1) {
        int add = (t >= d) ? sh[t - d] : 0;
        __syncthreads();
        sh[t] += add;
        __syncthreads();
    }
    g_bsum[t] = sh[t] - v;  // exclusive prefix
}

__global__ __launch_bounds__(256) void offsets_kernel(int nnodes)
{
    __shared__ int sh[256];
    int t = threadIdx.x;
    int n = blockIdx.x * 256 + t;
    int c = (n < nnodes) ? g_cnt[n] : 0;
    sh[t] = c;
    __syncthreads();
    #pragma unroll
    for (int d = 1; d < 256; d <<= 1) {
        int add = (t >= d) ? sh[t - d] : 0;
        __syncthreads();
        sh[t] += add;
        __syncthreads();
    }
    if (n < nnodes) {
        int off = g_bsum[blockIdx.x] + sh[t] - c;
        g_off[n] = off;
        g_cur[n] = off;
    }
}

__global__ void fill_kernel(const int* __restrict__ src,
                            const int* __restrict__ tgt,
                            const float* __restrict__ norm, int nedges)
{
    int e = blockIdx.x * blockDim.x + threadIdx.x;
    if (e >= nedges) return;
    int t = tgt[e];
    int pos = atomicAdd(&g_cur[t], 1);
    g_psrc[pos]  = src[e];
    g_pnorm[pos] = norm[e];
}

// ---------------------------------------------------------------------------
// Pool: warp per node. pooled[n] = sum_{edges into n} norm * H1[src].
// Lane l owns floats [l*4, l*4+4). 1-deep software pipeline on the gather.
// ---------------------------------------------------------------------------
__global__ __launch_bounds__(256) void pool_kernel(int nnodes)
{
    int n = blockIdx.x * 8 + (threadIdx.x >> 5);
    if (n >= nnodes) return;
    int lane = threadIdx.x & 31;

    int off = g_off[n];
    int cnt = g_cnt[n];

    float4 acc = make_float4(0.f, 0.f, 0.f, 0.f);
    if (cnt > 0) {
        int   s  = g_psrc[off];
        float nm = g_pnorm[off];
        float4 v = *(const float4*)&g_H1[(size_t)s * HID + lane * 4];
        for (int j = 1; j < cnt; j++) {
            int   s2  = g_psrc[off + j];
            float nm2 = g_pnorm[off + j];
            float4 v2 = *(const float4*)&g_H1[(size_t)s2 * HID + lane * 4];
            acc.x = fmaf(nm, v.x, acc.x);
            acc.y = fmaf(nm, v.y, acc.y);
            acc.z = fmaf(nm, v.z, acc.z);
            acc.w = fmaf(nm, v.w, acc.w);
            v = v2; nm = nm2;
        }
        acc.x = fmaf(nm, v.x, acc.x);
        acc.y = fmaf(nm, v.y, acc.y);
        acc.z = fmaf(nm, v.z, acc.z);
        acc.w = fmaf(nm, v.w, acc.w);
    }
    *(float4*)&g_pooled[(size_t)n * HID + lane * 4] = acc;
}

// ---------------------------------------------------------------------------
// Launch
// ---------------------------------------------------------------------------
extern "C" void kernel_launch(void* const* d_in, const int* in_sizes, int n_in,
                              void* d_out, int out_size)
{
    const float* nf   = (const float*)d_in[0];
    const int*   src  = (const int*)d_in[1];
    const int*   tgt  = (const int*)d_in[2];
    const float* norm = (const float*)d_in[3];
    const float* W1   = (const float*)d_in[4];
    const float* b1   = (const float*)d_in[5];
    const float* W2   = (const float*)d_in[6];
    const float* b2   = (const float*)d_in[7];
    float*       out  = (float*)d_out;

    const int nnodes = in_sizes[0] / HID;
    const int nedges = in_sizes[1];
    const int nchunk = (nnodes + 255) / 256;

    const size_t smem = (size_t)(HID * HID + HID * XPAD) * sizeof(float); // ~99KB
    cudaFuncSetAttribute(gemm_relu_kernel<false>,
                         cudaFuncAttributeMaxDynamicSharedMemorySize, (int)smem);
    cudaFuncSetAttribute(gemm_relu_kernel<true>,
                         cudaFuncAttributeMaxDynamicSharedMemorySize, (int)smem);

    float *H1 = nullptr, *pooled = nullptr;
    cudaGetSymbolAddress((void**)&H1, g_H1);
    cudaGetSymbolAddress((void**)&pooled, g_pooled);

    const int gblocks = (nnodes + 63) / 64;

    // GEMM1: H1 = relu(nf @ W1 + b1)
    gemm_relu_kernel<false><<<gblocks, 256, smem>>>(nf, W1, b1, nullptr, H1, nnodes);

    // CSR build (independent of GEMM1; serialized on the default stream)
    zero_cnt_kernel<<<(nnodes + 255) / 256, 256>>>(nnodes);
    hist_kernel<<<(nedges + 255) / 256, 256>>>(tgt, nedges);
    bsum_kernel<<<nchunk, 256>>>(nnodes);
    scan_bsum_kernel<<<1, 256>>>(nchunk);
    offsets_kernel<<<nchunk, 256>>>(nnodes);
    fill_kernel<<<(nedges + 255) / 256, 256>>>(src, tgt, norm, nedges);

    // Pool: pooled[n] = sum norm * H1[src]
    pool_kernel<<<(nnodes + 7) / 8, 256>>>(nnodes);

    // GEMM2: out = relu(pooled @ W2 + b2) + nf
    gemm_relu_kernel<true><<<gblocks, 256, smem>>>(pooled, W2, b2, nf, out, nnodes);
}